// round 10
// baseline (speedup 1.0000x reference)
#include <cuda_runtime.h>
#include <cuda_fp16.h>
#include <cstdint>
#include <cstring>

// Problem shape (fixed by the dataset)
#define NPTS   4096
#define NS     16384
#define CH     256
#define CSKIP  128
#define DIN    384
#define HID    256
#define BMAX   8

// GEMM tiling (fp16 mma.m16n8k16)
#define BM 128
#define BN 128
#define BK 64
#define ROWB 144                 // smem row stride in bytes (64 halfs + 8 pad)
#define STAGEB (BM * ROWB)       // 18432 B per operand per stage
#define NSTG 3
#define SMEM_GEMM (NSTG * 2 * STAGEB)   // 110592 B

// Scratch (static device globals; no allocation allowed)
__device__ __half g_y[NS * DIN];       // interpolated+concat features (fp16)
__device__ __half g_h[NS * HID];       // hidden activations (fp16)
__device__ __half g_w1t[HID * DIN];    // W1^T [N,K] fp16
__device__ __half g_w2t[HID * HID];    // W2^T [N,K] fp16
__device__ int    g_idx[NS * 3];
__device__ float  g_w[NS * 3];
__device__ int    g_bstart[BMAX + 1];

// ===========================================================================
// helpers
// ===========================================================================
__device__ __forceinline__ uint32_t smem_u32(const void* p) {
    uint32_t a;
    asm("{ .reg .u64 t; cvta.to.shared.u64 t, %1; cvt.u32.u64 %0, t; }"
        : "=r"(a) : "l"(p));
    return a;
}
__device__ __forceinline__ void cp16(uint32_t sdst, const void* gsrc) {
    asm volatile("cp.async.ca.shared.global [%0], [%1], 16;"
                 :: "r"(sdst), "l"(gsrc));
}
#define CP_COMMIT() asm volatile("cp.async.commit_group;" ::: "memory")
#define CP_WAIT1()  asm volatile("cp.async.wait_group 1;"  ::: "memory")

__device__ __forceinline__ void ldsm4(uint32_t r[4], uint32_t addr) {
    asm volatile("ldmatrix.sync.aligned.m8n8.x4.shared.b16 {%0,%1,%2,%3}, [%4];"
                 : "=r"(r[0]), "=r"(r[1]), "=r"(r[2]), "=r"(r[3]) : "r"(addr));
}
__device__ __forceinline__ void mma_f16(float c[4], const uint32_t a[4],
                                        const uint32_t b0, const uint32_t b1) {
    asm volatile(
        "mma.sync.aligned.m16n8k16.row.col.f32.f16.f16.f32 "
        "{%0,%1,%2,%3}, {%4,%5,%6,%7}, {%8,%9}, {%0,%1,%2,%3};"
        : "+f"(c[0]), "+f"(c[1]), "+f"(c[2]), "+f"(c[3])
        : "r"(a[0]), "r"(a[1]), "r"(a[2]), "r"(a[3]), "r"(b0), "r"(b1));
}

// ===========================================================================
// 1) batch segment boundaries (batch is sorted)
// ===========================================================================
__global__ void seg_kernel(const int* __restrict__ batch, int n) {
    int j = blockIdx.x * blockDim.x + threadIdx.x;
    if (j >= n) return;
    int b  = batch[j];
    int bp = (j == 0) ? -1 : batch[j - 1];
    for (int v = bp + 1; v <= b; v++) g_bstart[v] = j;
    if (j == n - 1) {
        for (int v = b + 1; v <= BMAX; v++) g_bstart[v] = n;
    }
}

// ===========================================================================
// 2) kNN (K=3); block loads only the batch-segment range it needs
// ===========================================================================
__global__ void knn_kernel(const float* __restrict__ pos,
                           const float* __restrict__ pos_skip,
                           const int* __restrict__ batch_skip) {
    extern __shared__ float4 s_pts[];
    int tid = threadIdx.x;
    int t0 = blockIdx.x * blockDim.x;

    int qb_first = batch_skip[t0];
    int qb_last  = batch_skip[t0 + blockDim.x - 1];
    int jmin = g_bstart[qb_first];
    int jmax = g_bstart[qb_last + 1];

    for (int j = jmin + tid; j < jmax; j += blockDim.x) {
        float4 p;
        p.x = pos[3 * j + 0];
        p.y = pos[3 * j + 1];
        p.z = pos[3 * j + 2];
        p.w = 0.0f;
        s_pts[j - jmin] = p;
    }
    __syncthreads();

    int t = t0 + tid;
    float qx = pos_skip[3 * t + 0];
    float qy = pos_skip[3 * t + 1];
    float qz = pos_skip[3 * t + 2];
    int   qb = batch_skip[t];
    int j0 = g_bstart[qb] - jmin;
    int j1 = g_bstart[qb + 1] - jmin;

    float b0 = 3.0e38f, b1 = 3.0e38f, b2 = 3.0e38f;
    int   i0 = j0, i1 = j0, i2 = j0;

    #pragma unroll 4
    for (int j = j0; j < j1; j++) {
        float4 p = s_pts[j];
        float dx = p.x - qx;
        float dy = p.y - qy;
        float dz = p.z - qz;
        float d = fmaf(dx, dx, fmaf(dy, dy, dz * dz));
        if (d < b2) {
            if (d < b1) {
                if (d < b0) {
                    b2 = b1; i2 = i1; b1 = b0; i1 = i0; b0 = d; i0 = j;
                } else {
                    b2 = b1; i2 = i1; b1 = d; i1 = j;
                }
            } else {
                b2 = d; i2 = j;
            }
        }
    }

    float w0 = 1.0f / fmaxf(b0, 1e-16f);
    float w1 = 1.0f / fmaxf(b1, 1e-16f);
    float w2 = 1.0f / fmaxf(b2, 1e-16f);
    float inv = 1.0f / (w0 + w1 + w2);
    g_w[3 * t + 0] = w0 * inv;
    g_w[3 * t + 1] = w1 * inv;
    g_w[3 * t + 2] = w2 * inv;
    g_idx[3 * t + 0] = i0 + jmin;
    g_idx[3 * t + 1] = i1 + jmin;
    g_idx[3 * t + 2] = i2 + jmin;
}

// ===========================================================================
// 3) both weight transposes in ONE launch; fp16 output  W[K,N] -> Wt[N,K]
// ===========================================================================
__global__ void transpose_both(const float* __restrict__ W1, __half* __restrict__ W1t,
                               const float* __restrict__ W2, __half* __restrict__ W2t) {
    __shared__ float tile[32][33];
    const float* W; __half* Wt; int K, k0;
    int bx = blockIdx.x;
    if (bx < DIN / 32) { W = W1; Wt = W1t; K = DIN; k0 = bx * 32; }
    else               { W = W2; Wt = W2t; K = HID; k0 = (bx - DIN / 32) * 32; }
    int n0 = blockIdx.y * 32;
    int tx = threadIdx.x, ty = threadIdx.y;
    for (int i = ty; i < 32; i += 8)
        tile[i][tx] = W[(size_t)(k0 + i) * HID + n0 + tx];
    __syncthreads();
    for (int i = ty; i < 32; i += 8)
        Wt[(size_t)(n0 + i) * K + k0 + tx] = __float2half_rn(tile[tx][i]);
}

// ===========================================================================
// 3b) interpolate + concat -> g_y[NS, DIN] fp16, fully coalesced
//     one block (192 threads) per fine row; thread c covers cols 2c, 2c+1
// ===========================================================================
__global__ void __launch_bounds__(192)
interp_kernel(const float* __restrict__ x, const float* __restrict__ xs) {
    int t = blockIdx.x;
    int c = threadIdx.x;             // 0..191
    int col = 2 * c;
    __half2* yrow = (__half2*)(g_y + (size_t)t * DIN);
    if (col < CH) {
        int   i0 = g_idx[3 * t],  i1 = g_idx[3 * t + 1], i2 = g_idx[3 * t + 2];
        float w0 = g_w[3 * t],    w1 = g_w[3 * t + 1],   w2 = g_w[3 * t + 2];
        float2 a0 = *(const float2*)(x + (size_t)i0 * CH + col);
        float2 a1 = *(const float2*)(x + (size_t)i1 * CH + col);
        float2 a2 = *(const float2*)(x + (size_t)i2 * CH + col);
        float vx = w0 * a0.x + w1 * a1.x + w2 * a2.x;
        float vy = w0 * a0.y + w1 * a1.y + w2 * a2.y;
        yrow[c] = __floats2half2_rn(vx, vy);
    } else {
        float2 s = *(const float2*)(xs + (size_t)t * CSKIP + (col - CH));
        yrow[c] = __floats2half2_rn(s.x, s.y);
    }
}

// ===========================================================================
// 4) fp16 mma.sync GEMM + bias + ReLU, 3-stage cp.async pipeline.
//    C[M, 256] = relu(A[M,K] @ Wt^T + bias)
// ===========================================================================
template<int KTOT, bool EPI_HALF>
__global__ void __launch_bounds__(256, 2)
gemm_mma(const __half* __restrict__ A,
         const __half* __restrict__ Wt,
         const float* __restrict__ bias,
         void* __restrict__ Cv) {
    extern __shared__ char smem[];

    const int tid  = threadIdx.x;
    const int wid  = tid >> 5, lane = tid & 31;
    const int gid  = lane >> 2, tg = lane & 3;
    const int g8   = lane >> 3, r8 = lane & 7;     // ldmatrix lane groups
    const int wm0  = (wid & 3) * 32;               // 4 warps along M
    const int wn0  = (wid >> 2) * 64;              // 2 warps along N
    const int m0   = blockIdx.x * BM;
    const int n0   = blockIdx.y * BN;

    const int lrow  = tid >> 1;                    // 0..127
    const int lkoff = (tid & 1) * 32;              // half offset within BK=64

    float acc[2][8][4];
    #pragma unroll
    for (int mt = 0; mt < 2; mt++)
        #pragma unroll
        for (int nt = 0; nt < 8; nt++)
            #pragma unroll
            for (int q = 0; q < 4; q++) acc[mt][nt][q] = 0.0f;

    constexpr int T = KTOT / BK;

    auto issue = [&](int t) {
        if (t >= T) return;
        int s  = t % NSTG;
        int k0 = t * BK;
        char* dA = smem + s * (2 * STAGEB);
        char* dB = dA + STAGEB;
        {
            const __half* src = A + (size_t)(m0 + lrow) * KTOT + k0 + lkoff;
            uint32_t dst = smem_u32(dA + lrow * ROWB + lkoff * 2);
            #pragma unroll
            for (int j = 0; j < 4; j++) cp16(dst + j * 16, src + j * 8);
        }
        {
            const __half* src = Wt + (size_t)(n0 + lrow) * KTOT + k0 + lkoff;
            uint32_t dst = smem_u32(dB + lrow * ROWB + lkoff * 2);
            #pragma unroll
            for (int j = 0; j < 4; j++) cp16(dst + j * 16, src + j * 8);
        }
    };

    issue(0); CP_COMMIT();
    issue(1); CP_COMMIT();

    // per-lane ldmatrix base offsets (within a stage)
    const uint32_t aLane = (uint32_t)(((g8 & 1) * 8 + r8) * ROWB + (g8 >> 1) * 16);
    const uint32_t bLane = (uint32_t)(((g8 >> 1) * 8 + r8) * ROWB + (g8 & 1) * 16);
    const uint32_t sbase = smem_u32(smem);

    for (int t = 0; t < T; t++) {
        CP_WAIT1();
        __syncthreads();
        issue(t + 2); CP_COMMIT();

        int s = t % NSTG;
        uint32_t aB0 = sbase + s * (2 * STAGEB) + (uint32_t)(wm0 * ROWB) + aLane;
        uint32_t bB0 = sbase + s * (2 * STAGEB) + STAGEB + (uint32_t)(wn0 * ROWB) + bLane;

        #pragma unroll
        for (int ks = 0; ks < 4; ks++) {          // 4 x k16
            uint32_t koff = ks * 32;              // 16 halfs = 32B
            uint32_t af[2][4];
            #pragma unroll
            for (int mt = 0; mt < 2; mt++)
                ldsm4(af[mt], aB0 + (uint32_t)(mt * 16 * ROWB) + koff);
            uint32_t bf[4][4];
            #pragma unroll
            for (int ntp = 0; ntp < 4; ntp++)
                ldsm4(bf[ntp], bB0 + (uint32_t)(ntp * 16 * ROWB) + koff);
            #pragma unroll
            for (int mt = 0; mt < 2; mt++)
                #pragma unroll
                for (int ntp = 0; ntp < 4; ntp++) {
                    mma_f16(acc[mt][2 * ntp],     af[mt], bf[ntp][0], bf[ntp][1]);
                    mma_f16(acc[mt][2 * ntp + 1], af[mt], bf[ntp][2], bf[ntp][3]);
                }
        }
        __syncthreads();
    }

    // epilogue: bias + relu
    #pragma unroll
    for (int mt = 0; mt < 2; mt++) {
        int r0 = m0 + wm0 + mt * 16 + gid;
        #pragma unroll
        for (int nt = 0; nt < 8; nt++) {
            int col = n0 + wn0 + nt * 8 + tg * 2;
            float bv0 = __ldg(bias + col);
            float bv1 = __ldg(bias + col + 1);
            float v0 = fmaxf(acc[mt][nt][0] + bv0, 0.0f);
            float v1 = fmaxf(acc[mt][nt][1] + bv1, 0.0f);
            float v2 = fmaxf(acc[mt][nt][2] + bv0, 0.0f);
            float v3 = fmaxf(acc[mt][nt][3] + bv1, 0.0f);
            if (EPI_HALF) {
                __half* C = (__half*)Cv;
                *(__half2*)(C + (size_t)r0 * 256 + col)       = __floats2half2_rn(v0, v1);
                *(__half2*)(C + (size_t)(r0 + 8) * 256 + col) = __floats2half2_rn(v2, v3);
            } else {
                float* C = (float*)Cv;
                *(float2*)(C + (size_t)r0 * 256 + col)       = make_float2(v0, v1);
                *(float2*)(C + (size_t)(r0 + 8) * 256 + col) = make_float2(v2, v3);
            }
        }
    }
}

// ===========================================================================
// 5) tuple tail: pos_skip + batch_skip (as float)
// ===========================================================================
__global__ void tail_kernel(const float* __restrict__ pos_skip,
                            const int* __restrict__ batch_skip,
                            float* __restrict__ out, int write_batch) {
    int i = blockIdx.x * blockDim.x + threadIdx.x;
    if (i < NS * 3) out[(size_t)NS * HID + i] = pos_skip[i];
    if (write_batch && i < NS)
        out[(size_t)NS * HID + (size_t)NS * 3 + i] = (float)batch_skip[i];
}

// ===========================================================================
extern "C" void kernel_launch(void* const* d_in, const int* in_sizes, int n_in,
                              void* d_out, int out_size) {
    const float* x          = (const float*)d_in[0];
    const float* pos        = (const float*)d_in[1];
    const int*   batch      = (const int*)  d_in[2];
    const float* x_skip     = (const float*)d_in[3];
    const float* pos_skip   = (const float*)d_in[4];
    const int*   batch_skip = (const int*)  d_in[5];
    const float* W1         = (const float*)d_in[6];
    const float* b1         = (const float*)d_in[7];
    const float* W2         = (const float*)d_in[8];
    const float* b2         = (const float*)d_in[9];
    float* out = (float*)d_out;

    __half *p_y, *p_h, *p_w1t, *p_w2t;
    cudaGetSymbolAddress((void**)&p_y,   g_y);
    cudaGetSymbolAddress((void**)&p_h,   g_h);
    cudaGetSymbolAddress((void**)&p_w1t, g_w1t);
    cudaGetSymbolAddress((void**)&p_w2t, g_w2t);

    // 1) batch segments
    seg_kernel<<<(NPTS + 255) / 256, 256>>>(batch, NPTS);

    // 2) kNN
    size_t knn_smem = (size_t)NPTS * sizeof(float4);
    cudaFuncSetAttribute(knn_kernel, cudaFuncAttributeMaxDynamicSharedMemorySize,
                         (int)knn_smem);
    knn_kernel<<<NS / 128, 128, knn_smem>>>(pos, pos_skip, batch_skip);

    // 3) weight transposes (fp16) + coalesced interp/concat
    {
        dim3 b(32, 8);
        transpose_both<<<dim3(DIN / 32 + HID / 32, HID / 32), b>>>(
            W1, p_w1t, W2, p_w2t);
    }
    interp_kernel<<<NS, 192>>>(x, x_skip);

    // 4) MLP on tensor cores (fp16 mma, 3-stage pipeline)
    cudaFuncSetAttribute(gemm_mma<DIN, true>,
                         cudaFuncAttributeMaxDynamicSharedMemorySize, SMEM_GEMM);
    cudaFuncSetAttribute(gemm_mma<HID, false>,
                         cudaFuncAttributeMaxDynamicSharedMemorySize, SMEM_GEMM);
    {
        dim3 grid(NS / BM, HID / BN);
        gemm_mma<DIN, true><<<grid, 256, SMEM_GEMM>>>(p_y, p_w1t, b1, (void*)p_h);
        gemm_mma<HID, false><<<grid, 256, SMEM_GEMM>>>(p_h, p_w2t, b2, (void*)out);
    }

    // 5) tuple tail
    long long need_pos   = (long long)NS * HID + (long long)NS * 3;
    long long need_batch = need_pos + NS;
    if ((long long)out_size >= need_pos) {
        int wb = ((long long)out_size >= need_batch) ? 1 : 0;
        tail_kernel<<<(NS * 3 + 255) / 256, 256>>>(pos_skip, batch_skip, out, wb);
    }
    (void)n_in; (void)in_sizes;
}

// round 12
// speedup vs baseline: 1.6839x; 1.6839x over previous
#include <cuda_runtime.h>
#include <cuda_fp16.h>
#include <cstdint>
#include <cstring>

// Problem shape (fixed by the dataset)
#define NPTS   4096
#define NS     16384
#define CH     256
#define CSKIP  128
#define DIN    384
#define HID    256
#define BMAX   8

// common GEMM constants
#define BK 64
#define ROWB 144                 // smem row stride in bytes (64 halfs + 8 pad)

// gemm1 (fused): BM=64, BN=256
#define BM1 64
#define ASTG1 (BM1 * ROWB)       // 9216
#define BSTG1 (256 * ROWB)       // 36864
#define STG1  (ASTG1 + BSTG1)    // 46080
#define SMEM_G1 (2 * STG1)       // 92160

// gemm2: BM=128, BN=128 (R8 proven config)
#define STAGEB (128 * ROWB)      // 18432
#define SMEM_G2 (4 * STAGEB)     // 73728

// Scratch (static device globals; no allocation allowed)
__device__ __half g_x16[NPTS * CH];    // x in fp16
__device__ __half g_xs16[NS * CSKIP];  // x_skip in fp16
__device__ __half g_h[NS * HID];       // hidden activations (fp16)
__device__ __half g_w1t[HID * DIN];    // W1^T [N,K] fp16
__device__ __half g_w2t[HID * HID];    // W2^T [N,K] fp16
__device__ int    g_idx[NS * 3];
__device__ float  g_w[NS * 3];
__device__ int    g_bstart[BMAX + 1];

// ===========================================================================
// helpers
// ===========================================================================
__device__ __forceinline__ uint32_t h2u(__half2 h) {
    uint32_t u; memcpy(&u, &h, 4); return u;
}
__device__ __forceinline__ __half2 u2h2(uint32_t u) {
    __half2 h; memcpy(&h, &u, 4); return h;
}
__device__ __forceinline__ uint32_t smem_u32(const void* p) {
    uint32_t a;
    asm("{ .reg .u64 t; cvta.to.shared.u64 t, %1; cvt.u32.u64 %0, t; }"
        : "=r"(a) : "l"(p));
    return a;
}
__device__ __forceinline__ void cp16(uint32_t sdst, const void* gsrc) {
    asm volatile("cp.async.ca.shared.global [%0], [%1], 16;"
                 :: "r"(sdst), "l"(gsrc));
}
#define CP_COMMIT() asm volatile("cp.async.commit_group;" ::: "memory")
#define CP_WAIT0()  asm volatile("cp.async.wait_group 0;"  ::: "memory")

__device__ __forceinline__ void ldsm4(uint32_t r[4], uint32_t addr) {
    asm volatile("ldmatrix.sync.aligned.m8n8.x4.shared.b16 {%0,%1,%2,%3}, [%4];"
                 : "=r"(r[0]), "=r"(r[1]), "=r"(r[2]), "=r"(r[3]) : "r"(addr));
}
__device__ __forceinline__ void mma_f16(float c[4], const uint32_t a[4],
                                        const uint32_t b0, const uint32_t b1) {
    asm volatile(
        "mma.sync.aligned.m16n8k16.row.col.f32.f16.f16.f32 "
        "{%0,%1,%2,%3}, {%4,%5,%6,%7}, {%8,%9}, {%0,%1,%2,%3};"
        : "+f"(c[0]), "+f"(c[1]), "+f"(c[2]), "+f"(c[3])
        : "r"(a[0]), "r"(a[1]), "r"(a[2]), "r"(a[3]), "r"(b0), "r"(b1));
}

// ===========================================================================
// 1) batch segment boundaries (batch is sorted)
// ===========================================================================
__global__ void seg_kernel(const int* __restrict__ batch, int n) {
    int j = blockIdx.x * blockDim.x + threadIdx.x;
    if (j >= n) return;
    int b  = batch[j];
    int bp = (j == 0) ? -1 : batch[j - 1];
    for (int v = bp + 1; v <= b; v++) g_bstart[v] = j;
    if (j == n - 1) {
        for (int v = b + 1; v <= BMAX; v++) g_bstart[v] = n;
    }
}

// ===========================================================================
// 2) kNN (K=3); block loads only the batch-segment range it needs
// ===========================================================================
__global__ void knn_kernel(const float* __restrict__ pos,
                           const float* __restrict__ pos_skip,
                           const int* __restrict__ batch_skip) {
    extern __shared__ float4 s_pts[];
    int tid = threadIdx.x;
    int t0 = blockIdx.x * blockDim.x;

    int qb_first = batch_skip[t0];
    int qb_last  = batch_skip[t0 + blockDim.x - 1];
    int jmin = g_bstart[qb_first];
    int jmax = g_bstart[qb_last + 1];

    for (int j = jmin + tid; j < jmax; j += blockDim.x) {
        float4 p;
        p.x = pos[3 * j + 0];
        p.y = pos[3 * j + 1];
        p.z = pos[3 * j + 2];
        p.w = 0.0f;
        s_pts[j - jmin] = p;
    }
    __syncthreads();

    int t = t0 + tid;
    float qx = pos_skip[3 * t + 0];
    float qy = pos_skip[3 * t + 1];
    float qz = pos_skip[3 * t + 2];
    int   qb = batch_skip[t];
    int j0 = g_bstart[qb] - jmin;
    int j1 = g_bstart[qb + 1] - jmin;

    float b0 = 3.0e38f, b1 = 3.0e38f, b2 = 3.0e38f;
    int   i0 = j0, i1 = j0, i2 = j0;

    #pragma unroll 4
    for (int j = j0; j < j1; j++) {
        float4 p = s_pts[j];
        float dx = p.x - qx;
        float dy = p.y - qy;
        float dz = p.z - qz;
        float d = fmaf(dx, dx, fmaf(dy, dy, dz * dz));
        if (d < b2) {
            if (d < b1) {
                if (d < b0) {
                    b2 = b1; i2 = i1; b1 = b0; i1 = i0; b0 = d; i0 = j;
                } else {
                    b2 = b1; i2 = i1; b1 = d; i1 = j;
                }
            } else {
                b2 = d; i2 = j;
            }
        }
    }

    float w0 = 1.0f / fmaxf(b0, 1e-16f);
    float w1 = 1.0f / fmaxf(b1, 1e-16f);
    float w2 = 1.0f / fmaxf(b2, 1e-16f);
    float inv = 1.0f / (w0 + w1 + w2);
    g_w[3 * t + 0] = w0 * inv;
    g_w[3 * t + 1] = w1 * inv;
    g_w[3 * t + 2] = w2 * inv;
    g_idx[3 * t + 0] = i0 + jmin;
    g_idx[3 * t + 1] = i1 + jmin;
    g_idx[3 * t + 2] = i2 + jmin;
}

// ===========================================================================
// 3a) fp32 -> fp16 bulk convert (pairs)
// ===========================================================================
__global__ void f32_to_f16(const float* __restrict__ src,
                           __half* __restrict__ dst, int n2) {
    int i = blockIdx.x * blockDim.x + threadIdx.x;
    if (i < n2) {
        float2 v = ((const float2*)src)[i];
        ((__half2*)dst)[i] = __floats2half2_rn(v.x, v.y);
    }
}

// ===========================================================================
// 3b) both weight transposes in ONE launch; fp16 output  W[K,N] -> Wt[N,K]
// ===========================================================================
__global__ void transpose_both(const float* __restrict__ W1, __half* __restrict__ W1t,
                               const float* __restrict__ W2, __half* __restrict__ W2t) {
    __shared__ float tile[32][33];
    const float* W; __half* Wt; int K, k0;
    int bx = blockIdx.x;
    if (bx < DIN / 32) { W = W1; Wt = W1t; K = DIN; k0 = bx * 32; }
    else               { W = W2; Wt = W2t; K = HID; k0 = (bx - DIN / 32) * 32; }
    int n0 = blockIdx.y * 32;
    int tx = threadIdx.x, ty = threadIdx.y;
    for (int i = ty; i < 32; i += 8)
        tile[i][tx] = W[(size_t)(k0 + i) * HID + n0 + tx];
    __syncthreads();
    for (int i = ty; i < 32; i += 8)
        Wt[(size_t)(n0 + i) * K + k0 + tx] = __float2half_rn(tile[tx][i]);
}

// ===========================================================================
// 4a) gemm1: fused interp+concat GEMM.  BM=64, BN=256 (full N, gather once).
//     g_h[M,256] = relu([interp(x16), xs16] @ W1t^T + b1)   fp16 out
// ===========================================================================
__global__ void __launch_bounds__(256, 2)
gemm1_fused(const float* __restrict__ bias, __half* __restrict__ C) {
    extern __shared__ char smem[];

    const int tid  = threadIdx.x;
    const int wid  = tid >> 5, lane = tid & 31;
    const int gid  = lane >> 2, tg = lane & 3;
    const int g8   = lane >> 3, r8 = lane & 7;
    const int wm0  = (wid & 1) * 32;               // 2 warps along M
    const int wn0  = (wid >> 1) * 64;              // 4 warps along N
    const int m0   = blockIdx.x * BM1;

    const int arow = tid >> 2;                     // 0..63
    const int koff = (tid & 3) * 16;               // halfs within BK=64

    const int m = m0 + arow;
    const int   i0 = g_idx[3 * m], i1 = g_idx[3 * m + 1], i2 = g_idx[3 * m + 2];
    const float w0 = g_w[3 * m],   w1 = g_w[3 * m + 1],   w2 = g_w[3 * m + 2];

    float acc[2][8][4];
    #pragma unroll
    for (int mt = 0; mt < 2; mt++)
        #pragma unroll
        for (int nt = 0; nt < 8; nt++)
            #pragma unroll
            for (int q = 0; q < 4; q++) acc[mt][nt][q] = 0.0f;

    constexpr int T = DIN / BK;   // 6

    auto issue = [&](int t) {
        int s  = t & 1;
        int k0 = t * BK;
        char* dA = smem + s * STG1;
        char* dB = dA + ASTG1;
        // B tile: all 256 rows of W1t, 64 halfs each; thread -> one row
        {
            const __half* src = g_w1t + (size_t)tid * DIN + k0;
            uint32_t dst = smem_u32(dB + tid * ROWB);
            #pragma unroll
            for (int j = 0; j < 8; j++) cp16(dst + j * 16, src + j * 8);
        }
        // A tile
        if (t < 4) {
            // gather 16 fp16 from each of 3 rows, weighted fp32 combine
            int kg = k0 + koff;
            const char* p0 = (const char*)(g_x16 + (size_t)i0 * CH + kg);
            const char* p1 = (const char*)(g_x16 + (size_t)i1 * CH + kg);
            const char* p2 = (const char*)(g_x16 + (size_t)i2 * CH + kg);
            uint4 A0 = *(const uint4*)p0, A1 = *(const uint4*)(p0 + 16);
            uint4 B0 = *(const uint4*)p1, B1 = *(const uint4*)(p1 + 16);
            uint4 D0 = *(const uint4*)p2, D1 = *(const uint4*)(p2 + 16);
            uint32_t o[8];
            #define CVT1(ax, bx, dx, oi) {                                     \
                float2 fa = __half22float2(u2h2(ax));                          \
                float2 fb = __half22float2(u2h2(bx));                          \
                float2 fd = __half22float2(u2h2(dx));                          \
                float vx = w0 * fa.x + w1 * fb.x + w2 * fd.x;                  \
                float vy = w0 * fa.y + w1 * fb.y + w2 * fd.y;                  \
                o[oi] = h2u(__floats2half2_rn(vx, vy)); }
            CVT1(A0.x, B0.x, D0.x, 0) CVT1(A0.y, B0.y, D0.y, 1)
            CVT1(A0.z, B0.z, D0.z, 2) CVT1(A0.w, B0.w, D0.w, 3)
            CVT1(A1.x, B1.x, D1.x, 4) CVT1(A1.y, B1.y, D1.y, 5)
            CVT1(A1.z, B1.z, D1.z, 6) CVT1(A1.w, B1.w, D1.w, 7)
            #undef CVT1
            char* d = dA + arow * ROWB + koff * 2;
            ((uint4*)d)[0] = make_uint4(o[0], o[1], o[2], o[3]);
            ((uint4*)d)[1] = make_uint4(o[4], o[5], o[6], o[7]);
        } else {
            // concat region: straight cp.async from fp16 x_skip
            const __half* src = g_xs16 + (size_t)m * CSKIP + (k0 - CH) + koff;
            uint32_t dst = smem_u32(dA + arow * ROWB + koff * 2);
            cp16(dst, src);
            cp16(dst + 16, src + 8);
        }
    };

    issue(0);
    CP_COMMIT();

    const uint32_t aLane = (uint32_t)(((g8 & 1) * 8 + r8) * ROWB + (g8 >> 1) * 16);
    const uint32_t bLane = (uint32_t)(((g8 >> 1) * 8 + r8) * ROWB + (g8 & 1) * 16);
    const uint32_t sbase = smem_u32(smem);

    for (int t = 0; t < T; t++) {
        CP_WAIT0();
        __syncthreads();
        if (t + 1 < T) { issue(t + 1); CP_COMMIT(); }

        int s = t & 1;
        uint32_t aB0 = sbase + s * STG1 + (uint32_t)(wm0 * ROWB) + aLane;
        uint32_t bB0 = sbase + s * STG1 + ASTG1 + (uint32_t)(wn0 * ROWB) + bLane;

        #pragma unroll
        for (int ks = 0; ks < 4; ks++) {
            uint32_t ko = ks * 32;
            uint32_t af[2][4];
            #pragma unroll
            for (int mt = 0; mt < 2; mt++)
                ldsm4(af[mt], aB0 + (uint32_t)(mt * 16 * ROWB) + ko);
            uint32_t bf[4][4];
            #pragma unroll
            for (int ntp = 0; ntp < 4; ntp++)
                ldsm4(bf[ntp], bB0 + (uint32_t)(ntp * 16 * ROWB) + ko);
            #pragma unroll
            for (int mt = 0; mt < 2; mt++)
                #pragma unroll
                for (int ntp = 0; ntp < 4; ntp++) {
                    mma_f16(acc[mt][2 * ntp],     af[mt], bf[ntp][0], bf[ntp][1]);
                    mma_f16(acc[mt][2 * ntp + 1], af[mt], bf[ntp][2], bf[ntp][3]);
                }
        }
    }

    // epilogue: bias + relu -> fp16
    #pragma unroll
    for (int mt = 0; mt < 2; mt++) {
        int r0 = m0 + wm0 + mt * 16 + gid;
        #pragma unroll
        for (int nt = 0; nt < 8; nt++) {
            int col = wn0 + nt * 8 + tg * 2;
            float bv0 = __ldg(bias + col);
            float bv1 = __ldg(bias + col + 1);
            float v0 = fmaxf(acc[mt][nt][0] + bv0, 0.0f);
            float v1 = fmaxf(acc[mt][nt][1] + bv1, 0.0f);
            float v2 = fmaxf(acc[mt][nt][2] + bv0, 0.0f);
            float v3 = fmaxf(acc[mt][nt][3] + bv1, 0.0f);
            *(__half2*)(C + (size_t)r0 * 256 + col)       = __floats2half2_rn(v0, v1);
            *(__half2*)(C + (size_t)(r0 + 8) * 256 + col) = __floats2half2_rn(v2, v3);
        }
    }
}

// ===========================================================================
// 4b) gemm2 (R8 proven): BM=128, BN=128, 2-stage.  out = relu(g_h @ W2t^T + b2)
// ===========================================================================
__global__ void __launch_bounds__(256, 2)
gemm2_kernel(const __half* __restrict__ A,
             const __half* __restrict__ Wt,
             const float* __restrict__ bias,
             float* __restrict__ C) {
    extern __shared__ char smem[];

    const int tid  = threadIdx.x;
    const int wid  = tid >> 5, lane = tid & 31;
    const int gid  = lane >> 2, tg = lane & 3;
    const int g8   = lane >> 3, r8 = lane & 7;
    const int wm0  = (wid & 3) * 32;
    const int wn0  = (wid >> 2) * 64;
    const int m0   = blockIdx.x * 128;
    const int n0   = blockIdx.y * 128;

    const int lrow  = tid >> 1;
    const int lkoff = (tid & 1) * 32;

    float acc[2][8][4];
    #pragma unroll
    for (int mt = 0; mt < 2; mt++)
        #pragma unroll
        for (int nt = 0; nt < 8; nt++)
            #pragma unroll
            for (int q = 0; q < 4; q++) acc[mt][nt][q] = 0.0f;

    constexpr int T = HID / BK;   // 4

    auto issue = [&](int t) {
        int s  = t & 1;
        int k0 = t * BK;
        char* dA = smem + s * (2 * STAGEB);
        char* dB = dA + STAGEB;
        {
            const __half* src = A + (size_t)(m0 + lrow) * HID + k0 + lkoff;
            uint32_t dst = smem_u32(dA + lrow * ROWB + lkoff * 2);
            #pragma unroll
            for (int j = 0; j < 4; j++) cp16(dst + j * 16, src + j * 8);
        }
        {
            const __half* src = Wt + (size_t)(n0 + lrow) * HID + k0 + lkoff;
            uint32_t dst = smem_u32(dB + lrow * ROWB + lkoff * 2);
            #pragma unroll
            for (int j = 0; j < 4; j++) cp16(dst + j * 16, src + j * 8);
        }
    };

    issue(0);
    CP_COMMIT();

    const uint32_t aLane = (uint32_t)(((g8 & 1) * 8 + r8) * ROWB + (g8 >> 1) * 16);
    const uint32_t bLane = (uint32_t)(((g8 >> 1) * 8 + r8) * ROWB + (g8 & 1) * 16);
    const uint32_t sbase = smem_u32(smem);

    for (int t = 0; t < T; t++) {
        CP_WAIT0();
        __syncthreads();
        if (t + 1 < T) { issue(t + 1); CP_COMMIT(); }

        int s = t & 1;
        uint32_t aB0 = sbase + s * (2 * STAGEB) + (uint32_t)(wm0 * ROWB) + aLane;
        uint32_t bB0 = sbase + s * (2 * STAGEB) + STAGEB + (uint32_t)(wn0 * ROWB) + bLane;

        #pragma unroll
        for (int ks = 0; ks < 4; ks++) {
            uint32_t ko = ks * 32;
            uint32_t af[2][4];
            #pragma unroll
            for (int mt = 0; mt < 2; mt++)
                ldsm4(af[mt], aB0 + (uint32_t)(mt * 16 * ROWB) + ko);
            uint32_t bf[4][4];
            #pragma unroll
            for (int ntp = 0; ntp < 4; ntp++)
                ldsm4(bf[ntp], bB0 + (uint32_t)(ntp * 16 * ROWB) + ko);
            #pragma unroll
            for (int mt = 0; mt < 2; mt++)
                #pragma unroll
                for (int ntp = 0; ntp < 4; ntp++) {
                    mma_f16(acc[mt][2 * ntp],     af[mt], bf[ntp][0], bf[ntp][1]);
                    mma_f16(acc[mt][2 * ntp + 1], af[mt], bf[ntp][2], bf[ntp][3]);
                }
        }
    }

    #pragma unroll
    for (int mt = 0; mt < 2; mt++) {
        int r0 = m0 + wm0 + mt * 16 + gid;
        #pragma unroll
        for (int nt = 0; nt < 8; nt++) {
            int col = n0 + wn0 + nt * 8 + tg * 2;
            float bv0 = __ldg(bias + col);
            float bv1 = __ldg(bias + col + 1);
            float v0 = fmaxf(acc[mt][nt][0] + bv0, 0.0f);
            float v1 = fmaxf(acc[mt][nt][1] + bv1, 0.0f);
            float v2 = fmaxf(acc[mt][nt][2] + bv0, 0.0f);
            float v3 = fmaxf(acc[mt][nt][3] + bv1, 0.0f);
            *(float2*)(C + (size_t)r0 * 256 + col)       = make_float2(v0, v1);
            *(float2*)(C + (size_t)(r0 + 8) * 256 + col) = make_float2(v2, v3);
        }
    }
}

// ===========================================================================
// 5) tuple tail: pos_skip + batch_skip (as float)
// ===========================================================================
__global__ void tail_kernel(const float* __restrict__ pos_skip,
                            const int* __restrict__ batch_skip,
                            float* __restrict__ out, int write_batch) {
    int i = blockIdx.x * blockDim.x + threadIdx.x;
    if (i < NS * 3) out[(size_t)NS * HID + i] = pos_skip[i];
    if (write_batch && i < NS)
        out[(size_t)NS * HID + (size_t)NS * 3 + i] = (float)batch_skip[i];
}

// ===========================================================================
extern "C" void kernel_launch(void* const* d_in, const int* in_sizes, int n_in,
                              void* d_out, int out_size) {
    const float* x          = (const float*)d_in[0];
    const float* pos        = (const float*)d_in[1];
    const int*   batch      = (const int*)  d_in[2];
    const float* x_skip     = (const float*)d_in[3];
    const float* pos_skip   = (const float*)d_in[4];
    const int*   batch_skip = (const int*)  d_in[5];
    const float* W1         = (const float*)d_in[6];
    const float* b1         = (const float*)d_in[7];
    const float* W2         = (const float*)d_in[8];
    const float* b2         = (const float*)d_in[9];
    float* out = (float*)d_out;

    __half *p_x16, *p_xs16, *p_h, *p_w1t, *p_w2t;
    cudaGetSymbolAddress((void**)&p_x16,  g_x16);
    cudaGetSymbolAddress((void**)&p_xs16, g_xs16);
    cudaGetSymbolAddress((void**)&p_h,    g_h);
    cudaGetSymbolAddress((void**)&p_w1t,  g_w1t);
    cudaGetSymbolAddress((void**)&p_w2t,  g_w2t);

    // 1) batch segments
    seg_kernel<<<(NPTS + 255) / 256, 256>>>(batch, NPTS);

    // 2) kNN
    size_t knn_smem = (size_t)NPTS * sizeof(float4);
    cudaFuncSetAttribute(knn_kernel, cudaFuncAttributeMaxDynamicSharedMemorySize,
                         (int)knn_smem);
    knn_kernel<<<NS / 128, 128, knn_smem>>>(pos, pos_skip, batch_skip);

    // 3) fp16 copies of x / x_skip, weight transposes
    f32_to_f16<<<(NPTS * CH / 2 + 511) / 512, 512>>>(x, p_x16, NPTS * CH / 2);
    f32_to_f16<<<(NS * CSKIP / 2 + 511) / 512, 512>>>(x_skip, p_xs16, NS * CSKIP / 2);
    {
        dim3 b(32, 8);
        transpose_both<<<dim3(DIN / 32 + HID / 32, HID / 32), b>>>(
            W1, p_w1t, W2, p_w2t);
    }

    // 4) MLP on tensor cores
    cudaFuncSetAttribute(gemm1_fused,
                         cudaFuncAttributeMaxDynamicSharedMemorySize, SMEM_G1);
    cudaFuncSetAttribute(gemm2_kernel,
                         cudaFuncAttributeMaxDynamicSharedMemorySize, SMEM_G2);
    gemm1_fused<<<NS / BM1, 256, SMEM_G1>>>(b1, p_h);
    gemm2_kernel<<<dim3(NS / 128, 2), 256, SMEM_G2>>>(p_h, p_w2t, b2, out);

    // 5) tuple tail
    long long need_pos   = (long long)NS * HID + (long long)NS * 3;
    long long need_batch = need_pos + NS;
    if ((long long)out_size >= need_pos) {
        int wb = ((long long)out_size >= need_batch) ? 1 : 0;
        tail_kernel<<<(NS * 3 + 255) / 256, 256>>>(pos_skip, batch_skip, out, wb);
    }
    (void)n_in; (void)in_sizes;
}